// round 3
// baseline (speedup 1.0000x reference)
#include <cuda_runtime.h>

// Problem constants
#define T_STEPS  200
#define BATCH    4096
#define HID      300
#define EMB      100
#define KTOT     400          // HID + EMB (concat GEMM depth)
#define JPAD     320          // hidden out padded to 320 (10 cols per lane x 32 lanes)
#define ROWS     32           // batch rows per CTA
#define NTHREADS 256
#define NBLOCKS  (BATCH / ROWS)   // 128
#define CHUNK_K  16
#define NCHUNK   (KTOT / CHUNK_K) // 25
#define AT_STRIDE 36          // padded row stride for a_t (16B-aligned float4 rows, r<=31)
#define WS_ELEMS (CHUNK_K * JPAD) // 5120 floats per weight chunk

// Persistent scratch (device globals: allocation-free per harness rules)
__device__ float g_WcatT[KTOT * JPAD];   // WcatT[k][j]: k<300 -> W_hh[j][k], k>=300 -> W_ih[j][k-300]; j>=300 -> 0
__device__ float g_W1T[HID * 256];       // W1T[k][m] = W1[m][k]

// ---------- f32x2 helpers (Blackwell packed fp32) ----------
__device__ __forceinline__ unsigned long long dup2(float x) {
    unsigned long long r;
    asm("mov.b64 %0, {%1, %1};" : "=l"(r) : "f"(x));
    return r;
}
__device__ __forceinline__ void fma2(unsigned long long& d, unsigned long long a, unsigned long long b) {
    asm("fma.rn.f32x2 %0, %1, %2, %0;" : "+l"(d) : "l"(a), "l"(b));
}
__device__ __forceinline__ void unpack2(unsigned long long v, float& lo, float& hi) {
    asm("mov.b64 {%0, %1}, %2;" : "=f"(lo), "=f"(hi) : "l"(v));
}

// ---------- cp.async helpers ----------
__device__ __forceinline__ void cp_async16(unsigned dst_smem, const void* src) {
    asm volatile("cp.async.ca.shared.global [%0], [%1], 16;" :: "r"(dst_smem), "l"(src));
}
__device__ __forceinline__ void cp_commit() { asm volatile("cp.async.commit_group;"); }
__device__ __forceinline__ void cp_wait0()  { asm volatile("cp.async.wait_group 0;"); }

// =======================================================================
// Init kernel: build WcatT (concat weights, transposed, padded) and W1T
// =======================================================================
__global__ void init_weights_kernel(const float* __restrict__ W_ih,
                                    const float* __restrict__ W_hh,
                                    const float* __restrict__ W1) {
    int idx = blockIdx.x * blockDim.x + threadIdx.x;
    if (idx < KTOT * JPAD) {
        int k = idx / JPAD;
        int j = idx - k * JPAD;
        float v = 0.0f;
        if (j < HID) {
            v = (k < HID) ? W_hh[j * HID + k] : W_ih[j * EMB + (k - HID)];
        }
        g_WcatT[idx] = v;
    }
    if (idx < HID * 256) {
        int k = idx >> 8;          // /256
        int m = idx & 255;
        g_W1T[idx] = W1[m * HID + k];
    }
}

// =======================================================================
// Main fused RNN kernel: 128 CTAs x 256 threads, each CTA owns 32 batch
// rows for all 200 timesteps. No inter-CTA communication.
// =======================================================================
__global__ void __launch_bounds__(NTHREADS, 1)
rnn_fused_kernel(const int* __restrict__ x,
                 const float* __restrict__ emb,
                 const float* __restrict__ b_ih,
                 const float* __restrict__ b_hh,
                 const float* __restrict__ b1,
                 const float* __restrict__ W2,
                 const float* __restrict__ b2,
                 float* __restrict__ out) {
    extern __shared__ float smem[];
    float* a_t   = smem;                                  // [KTOT][AT_STRIDE] transposed activations: a_t[k*36 + r]
    float* ws    = smem + KTOT * AT_STRIDE;               // [2][WS_ELEMS] double-buffered weight chunks
    float* biass = smem + KTOT * AT_STRIDE + 2 * WS_ELEMS;// [JPAD]
    float* y1s   = ws;                                    // alias: [32][256] FC1 activations (after step loop)

    const int tid = threadIdx.x;
    const int tx  = tid & 31;     // lane: column group (j = tx*10 + c)
    const int ty  = tid >> 5;     // warp: row group (r = ty*4 + rr)
    const int r0  = blockIdx.x * ROWS;

    // ---- Prologue: h(0)=0, combined bias ----
    for (int i = tid; i < HID * AT_STRIDE; i += NTHREADS) a_t[i] = 0.0f;
    for (int j = tid; j < JPAD; j += NTHREADS)
        biass[j] = (j < HID) ? (b_ih[j] + b_hh[j]) : 0.0f;
    __syncthreads();

    // Per-thread bias pairs (constant across steps)
    unsigned long long bpair[5];
#pragma unroll
    for (int c2 = 0; c2 < 5; c2++)
        bpair[c2] = *reinterpret_cast<const unsigned long long*>(&biass[tx * 10 + 2 * c2]);

    const unsigned ws0 = (unsigned)__cvta_generic_to_shared(ws);

    // ==================== timestep loop ====================
    for (int t = 0; t < T_STEPS; t++) {
        // ---- Fill embedding part of a_t: a_t[300+e][r] = emb[x[t,r0+r]][e] ----
        {
            const int* xt = x + t * BATCH + r0;
            // 32 rows x 25 float4 = 800 vector loads
            for (int idx = tid; idx < ROWS * 25; idx += NTHREADS) {
                int row = idx / 25;
                int q   = idx - row * 25;
                int tok = xt[row];
                float4 v = *reinterpret_cast<const float4*>(emb + (long long)tok * EMB + q * 4);
                int kb = HID + q * 4;
                a_t[(kb + 0) * AT_STRIDE + row] = v.x;
                a_t[(kb + 1) * AT_STRIDE + row] = v.y;
                a_t[(kb + 2) * AT_STRIDE + row] = v.z;
                a_t[(kb + 3) * AT_STRIDE + row] = v.w;
            }
        }

        // ---- init accumulators (bias already folded) ----
        unsigned long long acc[4][5];
#pragma unroll
        for (int rr = 0; rr < 4; rr++)
#pragma unroll
            for (int c2 = 0; c2 < 5; c2++) acc[rr][c2] = bpair[c2];

        // ---- stage chunk 0 ----
        int buf = 0;
#pragma unroll
        for (int i = 0; i < 5; i++) {
            int idx = tid + i * NTHREADS;            // float4 index, 1280 total
            cp_async16(ws0 + idx * 16, g_WcatT + idx * 4);
        }
        cp_commit();
        cp_wait0();
        __syncthreads();   // emb fill + prev-step h writes + chunk0 all visible

        // ---- K loop: 25 chunks of 16, double-buffered ----
        for (int cb = 0; cb < NCHUNK; cb++) {
            if (cb < NCHUNK - 1) {
                const float* src = g_WcatT + (cb + 1) * WS_ELEMS;
                unsigned dsts = ws0 + (unsigned)((buf ^ 1) * WS_ELEMS * 4);
#pragma unroll
                for (int i = 0; i < 5; i++) {
                    int idx = tid + i * NTHREADS;
                    cp_async16(dsts + idx * 16, src + idx * 4);
                }
                cp_commit();
            }

            const float* wb = ws + buf * WS_ELEMS;
#pragma unroll
            for (int kk = 0; kk < CHUNK_K; kk++) {
                const int k = cb * CHUNK_K + kk;
                const float4 h4 = *reinterpret_cast<const float4*>(a_t + k * AT_STRIDE + (ty << 2));
                unsigned long long hd0 = dup2(h4.x);
                unsigned long long hd1 = dup2(h4.y);
                unsigned long long hd2 = dup2(h4.z);
                unsigned long long hd3 = dup2(h4.w);
                const unsigned long long* wrow =
                    reinterpret_cast<const unsigned long long*>(wb + kk * JPAD + tx * 10);
                unsigned long long w0 = wrow[0], w1 = wrow[1], w2v = wrow[2], w3 = wrow[3], w4 = wrow[4];
                fma2(acc[0][0], hd0, w0); fma2(acc[0][1], hd0, w1); fma2(acc[0][2], hd0, w2v); fma2(acc[0][3], hd0, w3); fma2(acc[0][4], hd0, w4);
                fma2(acc[1][0], hd1, w0); fma2(acc[1][1], hd1, w1); fma2(acc[1][2], hd1, w2v); fma2(acc[1][3], hd1, w3); fma2(acc[1][4], hd1, w4);
                fma2(acc[2][0], hd2, w0); fma2(acc[2][1], hd2, w1); fma2(acc[2][2], hd2, w2v); fma2(acc[2][3], hd2, w3); fma2(acc[2][4], hd2, w4);
                fma2(acc[3][0], hd3, w0); fma2(acc[3][1], hd3, w1); fma2(acc[3][2], hd3, w2v); fma2(acc[3][3], hd3, w3); fma2(acc[3][4], hd3, w4);
            }

            if (cb < NCHUNK - 1) {
                cp_wait0();
                __syncthreads();
                buf ^= 1;
            }
        }
        __syncthreads();   // all GEMM reads of a_t / ws complete

        // ---- tanh + write h(t+1) back into a_t (transposed) ----
#pragma unroll
        for (int c2 = 0; c2 < 5; c2++) {
            int j0 = tx * 10 + 2 * c2;          // even; if j0<300 then j0+1<=299
            if (j0 < HID) {
                float lo0, hi0, lo1, hi1, lo2, hi2, lo3, hi3;
                unpack2(acc[0][c2], lo0, hi0);
                unpack2(acc[1][c2], lo1, hi1);
                unpack2(acc[2][c2], lo2, hi2);
                unpack2(acc[3][c2], lo3, hi3);
                float4 cl = make_float4(tanhf(lo0), tanhf(lo1), tanhf(lo2), tanhf(lo3));
                float4 ch = make_float4(tanhf(hi0), tanhf(hi1), tanhf(hi2), tanhf(hi3));
                *reinterpret_cast<float4*>(a_t + (j0    ) * AT_STRIDE + (ty << 2)) = cl;
                *reinterpret_cast<float4*>(a_t + (j0 + 1) * AT_STRIDE + (ty << 2)) = ch;
            }
        }
        // next iteration's pre-GEMM __syncthreads orders these writes
    }
    __syncthreads();   // final h visible to all

    // ==================== FC epilogue ====================
    // FC1: y1[r][m] = relu(b1[m] + sum_k h[r][k] * W1[m][k]); thread = m
    {
        const int m = tid;
        float acc32[32];
        float bb = b1[m];
#pragma unroll
        for (int r = 0; r < 32; r++) acc32[r] = bb;
        for (int k = 0; k < HID; k++) {
            float w = g_W1T[k * 256 + m];
            const float* hrow = a_t + k * AT_STRIDE;
#pragma unroll
            for (int r = 0; r < 32; r++) acc32[r] = fmaf(hrow[r], w, acc32[r]);
        }
#pragma unroll
        for (int r = 0; r < 32; r++) y1s[r * 256 + m] = fmaxf(acc32[r], 0.0f);
    }
    __syncthreads();

    // FC2: out[r][o] = b2[o] + sum_m y1[r][m] * W2[o][m]
    if (tid < 64) {
        int r = tid >> 1;
        int o = tid & 1;
        float s = b2[o];
        const float* w2r = W2 + o * 256;
        const float* yr  = y1s + r * 256;
#pragma unroll 8
        for (int m = 0; m < 256; m++) s = fmaf(yr[m], w2r[m], s);
        out[(r0 + r) * 2 + o] = s;
    }
}

// =======================================================================
// kernel_launch
// =======================================================================
extern "C" void kernel_launch(void* const* d_in, const int* in_sizes, int n_in,
                              void* d_out, int out_size) {
    const int*   x    = (const int*)  d_in[0];   // [200, 4096] int32
    const float* emb  = (const float*)d_in[1];   // [50000, 100]
    const float* W_ih = (const float*)d_in[2];   // [300, 100]
    const float* b_ih = (const float*)d_in[3];   // [300]
    const float* W_hh = (const float*)d_in[4];   // [300, 300]
    const float* b_hh = (const float*)d_in[5];   // [300]
    const float* W1   = (const float*)d_in[6];   // [256, 300]
    const float* b1   = (const float*)d_in[7];   // [256]
    const float* W2   = (const float*)d_in[8];   // [2, 256]
    const float* b2   = (const float*)d_in[9];   // [2]
    float* out = (float*)d_out;                  // [4096, 2]

    // Build transposed/padded weights (cheap; runs per replay, deterministic)
    init_weights_kernel<<<(KTOT * JPAD + 255) / 256, 256>>>(W_ih, W_hh, W1);

    const size_t smem_bytes = (size_t)(KTOT * AT_STRIDE + 2 * WS_ELEMS + JPAD) * sizeof(float); // 99,840 B
    cudaFuncSetAttribute(rnn_fused_kernel, cudaFuncAttributeMaxDynamicSharedMemorySize, (int)smem_bytes);

    rnn_fused_kernel<<<NBLOCKS, NTHREADS, smem_bytes>>>(x, emb, b_ih, b_hh, b1, W2, b2, out);
}

// round 4
// speedup vs baseline: 1.0001x; 1.0001x over previous
#include <cuda_runtime.h>

// Problem constants
#define T_STEPS  200
#define BATCH    4096
#define HID      300
#define EMB      100
#define KTOT     400          // HID + EMB (concat GEMM depth)
#define JPAD     320          // hidden out padded to 320 (10 cols per lane x 32 lanes)
#define ROWS     32           // batch rows per CTA
#define NTHREADS 256
#define NBLOCKS  (BATCH / ROWS)   // 128
#define CHUNK_K  16
#define NCHUNK   (KTOT / CHUNK_K) // 25
#define AT_STRIDE 36          // padded row stride for a_t (16B-aligned float4 rows, r<=31)
#define WS_ELEMS (CHUNK_K * JPAD) // 5120 floats per weight chunk

// Persistent scratch (device globals: allocation-free per harness rules)
__device__ float g_WcatT[KTOT * JPAD];   // WcatT[k][j]: k<300 -> W_hh[j][k], k>=300 -> W_ih[j][k-300]; j>=300 -> 0
__device__ float g_W1T[HID * 256];       // W1T[k][m] = W1[m][k]

// ---------- f32x2 helpers (Blackwell packed fp32) ----------
__device__ __forceinline__ unsigned long long dup2(float x) {
    unsigned long long r;
    asm("mov.b64 %0, {%1, %1};" : "=l"(r) : "f"(x));
    return r;
}
__device__ __forceinline__ void fma2(unsigned long long& d, unsigned long long a, unsigned long long b) {
    asm("fma.rn.f32x2 %0, %1, %2, %0;" : "+l"(d) : "l"(a), "l"(b));
}
__device__ __forceinline__ void unpack2(unsigned long long v, float& lo, float& hi) {
    asm("mov.b64 {%0, %1}, %2;" : "=f"(lo), "=f"(hi) : "l"(v));
}

// ---------- cp.async helpers ----------
__device__ __forceinline__ void cp_async16(unsigned dst_smem, const void* src) {
    asm volatile("cp.async.ca.shared.global [%0], [%1], 16;" :: "r"(dst_smem), "l"(src));
}
__device__ __forceinline__ void cp_commit() { asm volatile("cp.async.commit_group;"); }
__device__ __forceinline__ void cp_wait0()  { asm volatile("cp.async.wait_group 0;"); }

// =======================================================================
// Init kernel: build WcatT (concat weights, transposed, padded) and W1T
// =======================================================================
__global__ void init_weights_kernel(const float* __restrict__ W_ih,
                                    const float* __restrict__ W_hh,
                                    const float* __restrict__ W1) {
    int idx = blockIdx.x * blockDim.x + threadIdx.x;
    if (idx < KTOT * JPAD) {
        int k = idx / JPAD;
        int j = idx - k * JPAD;
        float v = 0.0f;
        if (j < HID) {
            v = (k < HID) ? W_hh[j * HID + k] : W_ih[j * EMB + (k - HID)];
        }
        g_WcatT[idx] = v;
    }
    if (idx < HID * 256) {
        int k = idx >> 8;          // /256
        int m = idx & 255;
        g_W1T[idx] = W1[m * HID + k];
    }
}

// =======================================================================
// Main fused RNN kernel: 128 CTAs x 256 threads, each CTA owns 32 batch
// rows for all 200 timesteps. No inter-CTA communication.
// =======================================================================
__global__ void __launch_bounds__(NTHREADS, 1)
rnn_fused_kernel(const int* __restrict__ x,
                 const float* __restrict__ emb,
                 const float* __restrict__ b_ih,
                 const float* __restrict__ b_hh,
                 const float* __restrict__ b1,
                 const float* __restrict__ W2,
                 const float* __restrict__ b2,
                 float* __restrict__ out) {
    extern __shared__ float smem[];
    float* a_t   = smem;                                  // [KTOT][AT_STRIDE] transposed activations: a_t[k*36 + r]
    float* ws    = smem + KTOT * AT_STRIDE;               // [2][WS_ELEMS] double-buffered weight chunks
    float* biass = smem + KTOT * AT_STRIDE + 2 * WS_ELEMS;// [JPAD]
    float* y1s   = ws;                                    // alias: [32][256] FC1 activations (after step loop)

    const int tid = threadIdx.x;
    const int tx  = tid & 31;     // lane: column group (j = tx*10 + c)
    const int ty  = tid >> 5;     // warp: row group (r = ty*4 + rr)
    const int r0  = blockIdx.x * ROWS;

    // ---- Prologue: h(0)=0, combined bias ----
    for (int i = tid; i < HID * AT_STRIDE; i += NTHREADS) a_t[i] = 0.0f;
    for (int j = tid; j < JPAD; j += NTHREADS)
        biass[j] = (j < HID) ? (b_ih[j] + b_hh[j]) : 0.0f;
    __syncthreads();

    // Per-thread bias pairs (constant across steps)
    unsigned long long bpair[5];
#pragma unroll
    for (int c2 = 0; c2 < 5; c2++)
        bpair[c2] = *reinterpret_cast<const unsigned long long*>(&biass[tx * 10 + 2 * c2]);

    const unsigned ws0 = (unsigned)__cvta_generic_to_shared(ws);

    // ==================== timestep loop ====================
    for (int t = 0; t < T_STEPS; t++) {
        // ---- Fill embedding part of a_t: a_t[300+e][r] = emb[x[t,r0+r]][e] ----
        {
            const int* xt = x + t * BATCH + r0;
            // 32 rows x 25 float4 = 800 vector loads
            for (int idx = tid; idx < ROWS * 25; idx += NTHREADS) {
                int row = idx / 25;
                int q   = idx - row * 25;
                int tok = xt[row];
                float4 v = *reinterpret_cast<const float4*>(emb + (long long)tok * EMB + q * 4);
                int kb = HID + q * 4;
                a_t[(kb + 0) * AT_STRIDE + row] = v.x;
                a_t[(kb + 1) * AT_STRIDE + row] = v.y;
                a_t[(kb + 2) * AT_STRIDE + row] = v.z;
                a_t[(kb + 3) * AT_STRIDE + row] = v.w;
            }
        }

        // ---- init accumulators (bias already folded) ----
        unsigned long long acc[4][5];
#pragma unroll
        for (int rr = 0; rr < 4; rr++)
#pragma unroll
            for (int c2 = 0; c2 < 5; c2++) acc[rr][c2] = bpair[c2];

        // ---- stage chunk 0 ----
        int buf = 0;
#pragma unroll
        for (int i = 0; i < 5; i++) {
            int idx = tid + i * NTHREADS;            // float4 index, 1280 total
            cp_async16(ws0 + idx * 16, g_WcatT + idx * 4);
        }
        cp_commit();
        cp_wait0();
        __syncthreads();   // emb fill + prev-step h writes + chunk0 all visible

        // ---- K loop: 25 chunks of 16, double-buffered ----
        for (int cb = 0; cb < NCHUNK; cb++) {
            if (cb < NCHUNK - 1) {
                const float* src = g_WcatT + (cb + 1) * WS_ELEMS;
                unsigned dsts = ws0 + (unsigned)((buf ^ 1) * WS_ELEMS * 4);
#pragma unroll
                for (int i = 0; i < 5; i++) {
                    int idx = tid + i * NTHREADS;
                    cp_async16(dsts + idx * 16, src + idx * 4);
                }
                cp_commit();
            }

            const float* wb = ws + buf * WS_ELEMS;
#pragma unroll
            for (int kk = 0; kk < CHUNK_K; kk++) {
                const int k = cb * CHUNK_K + kk;
                const float4 h4 = *reinterpret_cast<const float4*>(a_t + k * AT_STRIDE + (ty << 2));
                unsigned long long hd0 = dup2(h4.x);
                unsigned long long hd1 = dup2(h4.y);
                unsigned long long hd2 = dup2(h4.z);
                unsigned long long hd3 = dup2(h4.w);
                const unsigned long long* wrow =
                    reinterpret_cast<const unsigned long long*>(wb + kk * JPAD + tx * 10);
                unsigned long long w0 = wrow[0], w1 = wrow[1], w2v = wrow[2], w3 = wrow[3], w4 = wrow[4];
                fma2(acc[0][0], hd0, w0); fma2(acc[0][1], hd0, w1); fma2(acc[0][2], hd0, w2v); fma2(acc[0][3], hd0, w3); fma2(acc[0][4], hd0, w4);
                fma2(acc[1][0], hd1, w0); fma2(acc[1][1], hd1, w1); fma2(acc[1][2], hd1, w2v); fma2(acc[1][3], hd1, w3); fma2(acc[1][4], hd1, w4);
                fma2(acc[2][0], hd2, w0); fma2(acc[2][1], hd2, w1); fma2(acc[2][2], hd2, w2v); fma2(acc[2][3], hd2, w3); fma2(acc[2][4], hd2, w4);
                fma2(acc[3][0], hd3, w0); fma2(acc[3][1], hd3, w1); fma2(acc[3][2], hd3, w2v); fma2(acc[3][3], hd3, w3); fma2(acc[3][4], hd3, w4);
            }

            if (cb < NCHUNK - 1) {
                cp_wait0();
                __syncthreads();
                buf ^= 1;
            }
        }
        __syncthreads();   // all GEMM reads of a_t / ws complete

        // ---- tanh + write h(t+1) back into a_t (transposed) ----
#pragma unroll
        for (int c2 = 0; c2 < 5; c2++) {
            int j0 = tx * 10 + 2 * c2;          // even; if j0<300 then j0+1<=299
            if (j0 < HID) {
                float lo0, hi0, lo1, hi1, lo2, hi2, lo3, hi3;
                unpack2(acc[0][c2], lo0, hi0);
                unpack2(acc[1][c2], lo1, hi1);
                unpack2(acc[2][c2], lo2, hi2);
                unpack2(acc[3][c2], lo3, hi3);
                float4 cl = make_float4(tanhf(lo0), tanhf(lo1), tanhf(lo2), tanhf(lo3));
                float4 ch = make_float4(tanhf(hi0), tanhf(hi1), tanhf(hi2), tanhf(hi3));
                *reinterpret_cast<float4*>(a_t + (j0    ) * AT_STRIDE + (ty << 2)) = cl;
                *reinterpret_cast<float4*>(a_t + (j0 + 1) * AT_STRIDE + (ty << 2)) = ch;
            }
        }
        // next iteration's pre-GEMM __syncthreads orders these writes
    }
    __syncthreads();   // final h visible to all

    // ==================== FC epilogue ====================
    // FC1: y1[r][m] = relu(b1[m] + sum_k h[r][k] * W1[m][k]); thread = m
    {
        const int m = tid;
        float acc32[32];
        float bb = b1[m];
#pragma unroll
        for (int r = 0; r < 32; r++) acc32[r] = bb;
        for (int k = 0; k < HID; k++) {
            float w = g_W1T[k * 256 + m];
            const float* hrow = a_t + k * AT_STRIDE;
#pragma unroll
            for (int r = 0; r < 32; r++) acc32[r] = fmaf(hrow[r], w, acc32[r]);
        }
#pragma unroll
        for (int r = 0; r < 32; r++) y1s[r * 256 + m] = fmaxf(acc32[r], 0.0f);
    }
    __syncthreads();

    // FC2: out[r][o] = b2[o] + sum_m y1[r][m] * W2[o][m]
    if (tid < 64) {
        int r = tid >> 1;
        int o = tid & 1;
        float s = b2[o];
        const float* w2r = W2 + o * 256;
        const float* yr  = y1s + r * 256;
#pragma unroll 8
        for (int m = 0; m < 256; m++) s = fmaf(yr[m], w2r[m], s);
        out[(r0 + r) * 2 + o] = s;
    }
}

// =======================================================================
// kernel_launch
// =======================================================================
extern "C" void kernel_launch(void* const* d_in, const int* in_sizes, int n_in,
                              void* d_out, int out_size) {
    const int*   x    = (const int*)  d_in[0];   // [200, 4096] int32
    const float* emb  = (const float*)d_in[1];   // [50000, 100]
    const float* W_ih = (const float*)d_in[2];   // [300, 100]
    const float* b_ih = (const float*)d_in[3];   // [300]
    const float* W_hh = (const float*)d_in[4];   // [300, 300]
    const float* b_hh = (const float*)d_in[5];   // [300]
    const float* W1   = (const float*)d_in[6];   // [256, 300]
    const float* b1   = (const float*)d_in[7];   // [256]
    const float* W2   = (const float*)d_in[8];   // [2, 256]
    const float* b2   = (const float*)d_in[9];   // [2]
    float* out = (float*)d_out;                  // [4096, 2]

    // Build transposed/padded weights (cheap; runs per replay, deterministic)
    init_weights_kernel<<<(KTOT * JPAD + 255) / 256, 256>>>(W_ih, W_hh, W1);

    const size_t smem_bytes = (size_t)(KTOT * AT_STRIDE + 2 * WS_ELEMS + JPAD) * sizeof(float); // 99,840 B
    cudaFuncSetAttribute(rnn_fused_kernel, cudaFuncAttributeMaxDynamicSharedMemorySize, (int)smem_bytes);

    rnn_fused_kernel<<<NBLOCKS, NTHREADS, smem_bytes>>>(x, emb, b_ih, b_hh, b1, W2, b2, out);
}